// round 3
// baseline (speedup 1.0000x reference)
#include <cuda_runtime.h>
#include <cstdint>

#define BB 32
#define KKS 10
#define TT 128
#define LLS 128
#define DD 1024
#define NTAG 32
#define SS (KKS*LLS)     // 1280
#define CH 20            // chunks of 64 support rows
#define CROWS 64
#define ASTR 132         // padded smem strides (floats), 16B-aligned
#define BSTR 136

typedef unsigned long long ull;

// ---------------- scratch (device globals; no allocation) ----------------
__device__ float  g_test_mean[BB*TT*DD];     // (B,T,D) 16 MB
__device__ int    g_list[BB*NTAG*256];       // per (b,tag) support-row index lists
__device__ int    g_cnt[BB*NTAG];
__device__ float2 g_cmin[BB*TT*CH];          // per-chunk (minval, idx-as-float)

// ---------------- kernel 1: test_mean = mean_k test_reps ----------------
__global__ void k_mean(const float* __restrict__ x){
    int idx = blockIdx.x*blockDim.x + threadIdx.x;
    const int n4 = BB*TT*DD/4;
    if (idx >= n4) return;
    int b   = idx / (TT*DD/4);
    int rem = idx - b*(TT*DD/4);
    const float4* p = (const float4*)x + (size_t)b*KKS*(TT*DD/4) + rem;
    float4 a = make_float4(0.f,0.f,0.f,0.f);
#pragma unroll
    for (int k=0;k<KKS;k++){
        float4 v = p[(size_t)k*(TT*DD/4)];
        a.x+=v.x; a.y+=v.y; a.z+=v.z; a.w+=v.w;
    }
    const float s = 1.0f/(float)KKS;
    a.x*=s; a.y*=s; a.z*=s; a.w*=s;
    ((float4*)g_test_mean)[idx] = a;
}

// ---------------- kernel 2: labels + deterministic per-tag index lists ----------------
__global__ __launch_bounds__(256) void k_labels(const float* __restrict__ tgt){
    __shared__ int lab[SS];
    int b = blockIdx.x, tid = threadIdx.x;
    for (int s = tid; s < SS; s += 256){
        const float* row = tgt + ((size_t)b*SS + s)*NTAG;
        float bv = row[0]; int bi = 0;
#pragma unroll
        for (int n=1;n<NTAG;n++){ float v=row[n]; if (v>bv){bv=v;bi=n;} }
        lab[s] = bi;
    }
    __syncthreads();
    if (tid < NTAG){
        int c = 0;
        int* lst = g_list + ((size_t)b*NTAG + tid)*256;
        for (int s=0;s<SS;s++) if (lab[s]==tid && c<256) lst[c++] = s;
        g_cnt[b*NTAG + tid] = c;
    }
}

// ---------------- kernel 3: prototypes = gather-sum / (count+1e-4) ----------------
// grid (B, NT); 256 threads; thread owns one float4 of D; 4-way batched gather for MLP.
__global__ __launch_bounds__(256) void k_proto(const float* __restrict__ sup,
                                               float* __restrict__ proto){
    int b = blockIdx.x, n = blockIdx.y, tid = threadIdx.x;
    __shared__ int sl[256];
    int cnt = g_cnt[b*NTAG + n];
    const int* lst = g_list + ((size_t)b*NTAG + n)*256;
    sl[tid] = (tid < cnt) ? lst[tid] : 0;
    __syncthreads();
    float4 acc = make_float4(0.f,0.f,0.f,0.f);
    const float4* base = (const float4*)(sup + (size_t)b*SS*DD) + tid;
    int j = 0;
    for (; j+4 <= cnt; j += 4){
        float4 v0 = base[(size_t)sl[j+0]*(DD/4)];
        float4 v1 = base[(size_t)sl[j+1]*(DD/4)];
        float4 v2 = base[(size_t)sl[j+2]*(DD/4)];
        float4 v3 = base[(size_t)sl[j+3]*(DD/4)];
        acc.x += (v0.x+v1.x) + (v2.x+v3.x);
        acc.y += (v0.y+v1.y) + (v2.y+v3.y);
        acc.z += (v0.z+v1.z) + (v2.z+v3.z);
        acc.w += (v0.w+v1.w) + (v2.w+v3.w);
    }
    for (; j < cnt; j++){
        float4 v = base[(size_t)sl[j]*(DD/4)];
        acc.x+=v.x; acc.y+=v.y; acc.z+=v.z; acc.w+=v.w;
    }
    float inv = 1.0f/((float)cnt + 1e-4f);
    acc.x*=inv; acc.y*=inv; acc.z*=inv; acc.w*=inv;
    ((float4*)(proto + ((size_t)b*NTAG + n)*DD))[tid] = acc;
}

// ---------------- kernel 4: fp32x2 SGEMM (128T x 64S x 1024) + chunk argmin ----------------
// grid (20 chunks, 32 batches); 256 threads; occupancy 2.
// Row-pair accumulators: A pairs load directly as ull (no dup movs);
// B stored PRE-DUPLICATED in smem so fma2 B operand loads as ull (no dup movs).
// thread (tx,ty): rows {ty*4..+3, 64+ty*4..+3}, cols {tx*4..+3}.
__global__ __launch_bounds__(256,2) void k_gemm(const float* __restrict__ sup){
    const int ch = blockIdx.x, b = blockIdx.y;
    const int tid = threadIdx.x;
    const int tx = tid & 15, ty = tid >> 4;
    __shared__ float As [2][16][ASTR];    // k-major test rows
    __shared__ float Bsd[2][16][BSTR];    // k-major support cols, duplicated pairs
    __shared__ float snorm[CROWS];

    const float* A  = g_test_mean + (size_t)b*TT*DD;
    const float* Bp = sup + ((size_t)b*SS + (size_t)ch*CROWS)*DD;

    // A loader: 512 float4/tile -> 2 per thread. B loader: 256 float4 -> 1 per thread.
    const int ia0 = tid, ia1 = tid + 256;
    const int am0 = ia0>>2, ak0 = (ia0&3)*4;
    const int am1 = ia1>>2, ak1 = (ia1&3)*4;
    const int bm  = tid>>2, bk  = (tid&3)*4;
    const float* pA0 = A  + (size_t)am0*DD + ak0;
    const float* pA1 = A  + (size_t)am1*DD + ak1;
    const float* pB  = Bp + (size_t)bm *DD + bk;

    ull acc[4][4];
#pragma unroll
    for (int i=0;i<4;i++)
#pragma unroll
        for (int c=0;c<4;c++) acc[i][c]=0ull;
    float nrm = 0.f;

    float4 ra0 = *(const float4*)pA0;
    float4 ra1 = *(const float4*)pA1;
    float4 rb  = *(const float4*)pB;
    nrm += rb.x*rb.x + rb.y*rb.y + rb.z*rb.z + rb.w*rb.w;
    As[0][ak0+0][am0]=ra0.x; As[0][ak0+1][am0]=ra0.y; As[0][ak0+2][am0]=ra0.z; As[0][ak0+3][am0]=ra0.w;
    As[0][ak1+0][am1]=ra1.x; As[0][ak1+1][am1]=ra1.y; As[0][ak1+2][am1]=ra1.z; As[0][ak1+3][am1]=ra1.w;
    Bsd[0][bk+0][2*bm]=rb.x; Bsd[0][bk+0][2*bm+1]=rb.x;
    Bsd[0][bk+1][2*bm]=rb.y; Bsd[0][bk+1][2*bm+1]=rb.y;
    Bsd[0][bk+2][2*bm]=rb.z; Bsd[0][bk+2][2*bm+1]=rb.z;
    Bsd[0][bk+3][2*bm]=rb.w; Bsd[0][bk+3][2*bm+1]=rb.w;
    __syncthreads();

    for (int kt=0; kt<DD/16; kt++){
        const int buf = kt & 1;
        if (kt < DD/16-1){
            const int off = (kt+1)*16;
            ra0 = *(const float4*)(pA0+off);
            ra1 = *(const float4*)(pA1+off);
            rb  = *(const float4*)(pB +off);
            nrm += rb.x*rb.x + rb.y*rb.y + rb.z*rb.z + rb.w*rb.w;
        }
#pragma unroll
        for (int kk=0;kk<16;kk++){
            const ull* ap0 = (const ull*)&As[buf][kk][ty*4];      // rows ty*4..+3 (2 pairs)
            const ull* ap1 = (const ull*)&As[buf][kk][64+ty*4];   // rows 64+ty*4..+3
            ull a0 = ap0[0], a1 = ap0[1];
            ull a2 = ap1[0], a3 = ap1[1];
            const ull* br = (const ull*)&Bsd[buf][kk][tx*8];      // 4 dup col pairs
            ull b0 = br[0], b1 = br[1], b2 = br[2], b3 = br[3];
            asm("fma.rn.f32x2 %0, %1, %2, %0;" : "+l"(acc[0][0]) : "l"(a0), "l"(b0));
            asm("fma.rn.f32x2 %0, %1, %2, %0;" : "+l"(acc[0][1]) : "l"(a0), "l"(b1));
            asm("fma.rn.f32x2 %0, %1, %2, %0;" : "+l"(acc[0][2]) : "l"(a0), "l"(b2));
            asm("fma.rn.f32x2 %0, %1, %2, %0;" : "+l"(acc[0][3]) : "l"(a0), "l"(b3));
            asm("fma.rn.f32x2 %0, %1, %2, %0;" : "+l"(acc[1][0]) : "l"(a1), "l"(b0));
            asm("fma.rn.f32x2 %0, %1, %2, %0;" : "+l"(acc[1][1]) : "l"(a1), "l"(b1));
            asm("fma.rn.f32x2 %0, %1, %2, %0;" : "+l"(acc[1][2]) : "l"(a1), "l"(b2));
            asm("fma.rn.f32x2 %0, %1, %2, %0;" : "+l"(acc[1][3]) : "l"(a1), "l"(b3));
            asm("fma.rn.f32x2 %0, %1, %2, %0;" : "+l"(acc[2][0]) : "l"(a2), "l"(b0));
            asm("fma.rn.f32x2 %0, %1, %2, %0;" : "+l"(acc[2][1]) : "l"(a2), "l"(b1));
            asm("fma.rn.f32x2 %0, %1, %2, %0;" : "+l"(acc[2][2]) : "l"(a2), "l"(b2));
            asm("fma.rn.f32x2 %0, %1, %2, %0;" : "+l"(acc[2][3]) : "l"(a2), "l"(b3));
            asm("fma.rn.f32x2 %0, %1, %2, %0;" : "+l"(acc[3][0]) : "l"(a3), "l"(b0));
            asm("fma.rn.f32x2 %0, %1, %2, %0;" : "+l"(acc[3][1]) : "l"(a3), "l"(b1));
            asm("fma.rn.f32x2 %0, %1, %2, %0;" : "+l"(acc[3][2]) : "l"(a3), "l"(b2));
            asm("fma.rn.f32x2 %0, %1, %2, %0;" : "+l"(acc[3][3]) : "l"(a3), "l"(b3));
        }
        if (kt < DD/16-1){
            const int nb = buf^1;
            As[nb][ak0+0][am0]=ra0.x; As[nb][ak0+1][am0]=ra0.y; As[nb][ak0+2][am0]=ra0.z; As[nb][ak0+3][am0]=ra0.w;
            As[nb][ak1+0][am1]=ra1.x; As[nb][ak1+1][am1]=ra1.y; As[nb][ak1+2][am1]=ra1.z; As[nb][ak1+3][am1]=ra1.w;
            Bsd[nb][bk+0][2*bm]=rb.x; Bsd[nb][bk+0][2*bm+1]=rb.x;
            Bsd[nb][bk+1][2*bm]=rb.y; Bsd[nb][bk+1][2*bm+1]=rb.y;
            Bsd[nb][bk+2][2*bm]=rb.z; Bsd[nb][bk+2][2*bm+1]=rb.z;
            Bsd[nb][bk+3][2*bm]=rb.w; Bsd[nb][bk+3][2*bm+1]=rb.w;
        }
        __syncthreads();
    }

    // support-row norms: reduce 4 partials (lanes tid&3) per row
    nrm += __shfl_xor_sync(0xffffffffu, nrm, 2);
    nrm += __shfl_xor_sync(0xffffffffu, nrm, 1);
    if ((tid & 3) == 0) snorm[tid>>2] = nrm;
    __syncthreads();

    // score = |s|^2 - 2*dot ; per-row chunk argmin, first-min tie-break
#pragma unroll
    for (int i=0;i<8;i++){
        const int rp = i>>1, hf = i&1;
        float bv = 3.4e38f; int bi = 1<<30;
#pragma unroll
        for (int c=0;c<4;c++){
            float2 d = *(float2*)&acc[rp][c];
            float dv = hf ? d.y : d.x;
            int n = tx*4 + c;
            float s = snorm[n] - 2.f*dv;
            if (s < bv || (s==bv && n < bi)) { bv=s; bi=n; }
        }
#pragma unroll
        for (int o=8;o;o>>=1){
            float ov = __shfl_down_sync(0xffffffffu, bv, o, 16);
            int   oi = __shfl_down_sync(0xffffffffu, bi, o, 16);
            if (ov < bv || (ov==bv && oi<bi)) { bv=ov; bi=oi; }
        }
        if (tx==0){
            int m = (i<4) ? (ty*4+i) : (64+ty*4+(i-4));
            g_cmin[((size_t)b*TT+m)*CH + ch] = make_float2(bv, __int_as_float(ch*CROWS + bi));
        }
    }
}

// ---------------- kernel 5: nn-reduce + scores GEMM fused ----------------
// grid (B, 2): 64 t-rows x 32 tags x K=1024 per block; 256 threads.
__global__ __launch_bounds__(256) void k_final(const float* __restrict__ tgt,
                                               const float* __restrict__ proto,
                                               float* __restrict__ outs){
    __shared__ float As[16][64];   // k-major test rows
    __shared__ float Bs[16][32];   // k-major proto rows
    __shared__ int   snn[64];
    int b = blockIdx.x, half = blockIdx.y, tid = threadIdx.x;
    const int trow = tid & 63, tg = tid >> 6;

    // fused nn reduction over 20 chunks (threads 0..63)
    if (tid < 64){
        const float2* e = &g_cmin[((size_t)b*TT + half*64 + tid)*CH];
        float2 v0 = e[0];
        float bv = v0.x; int bi = __float_as_int(v0.y);
#pragma unroll
        for (int c=1;c<CH;c++){
            float2 v = e[c];
            if (v.x < bv){ bv = v.x; bi = __float_as_int(v.y); }
        }
        snn[tid] = bi;
    }

    const float* Ab = g_test_mean + ((size_t)b*TT + half*64)*DD;
    const float* Pb = proto + (size_t)b*NTAG*DD;
    const int ar = tid>>2, ak = (tid&3)*4;

    ull acc[4];
#pragma unroll
    for (int i=0;i<4;i++) acc[i]=0ull;

    for (int kt=0; kt<DD/16; kt++){
        __syncthreads();
        {
            float4 va = *(const float4*)(Ab + (size_t)ar*DD + kt*16 + ak);
            As[ak+0][ar]=va.x; As[ak+1][ar]=va.y; As[ak+2][ar]=va.z; As[ak+3][ar]=va.w;
            if (tid < 128){
                float4 vb = *(const float4*)(Pb + (size_t)ar*DD + kt*16 + ak);
                Bs[ak+0][ar]=vb.x; Bs[ak+1][ar]=vb.y; Bs[ak+2][ar]=vb.z; Bs[ak+3][ar]=vb.w;
            }
        }
        __syncthreads();
#pragma unroll
        for (int kk=0;kk<16;kk++){
            float a = As[kk][trow];
            const ull* br = (const ull*)&Bs[kk][tg*8];
            ull aa;
            asm("mov.b64 %0, {%1, %1};" : "=l"(aa) : "f"(a));
#pragma unroll
            for (int i=0;i<4;i++)
                asm("fma.rn.f32x2 %0, %1, %2, %0;" : "+l"(acc[i]) : "l"(aa), "l"(br[i]));
        }
    }
    __syncthreads();

    int nn = snn[trow];
    const float4* tp = (const float4*)(tgt + ((size_t)b*SS + nn)*NTAG + tg*8);
    float4 t0 = tp[0], t1 = tp[1];
    float2 d0 = *(float2*)&acc[0], d1 = *(float2*)&acc[1];
    float2 d2 = *(float2*)&acc[2], d3 = *(float2*)&acc[3];
    float4 o0 = make_float4(t0.x+0.5f*d0.x, t0.y+0.5f*d0.y, t0.z+0.5f*d1.x, t0.w+0.5f*d1.y);
    float4 o1 = make_float4(t1.x+0.5f*d2.x, t1.y+0.5f*d2.y, t1.z+0.5f*d3.x, t1.w+0.5f*d3.y);
    float4* op = (float4*)(outs + ((size_t)b*TT + half*64 + trow)*NTAG + tg*8);
    op[0] = o0; op[1] = o1;
}

// ---------------- launch ----------------
extern "C" void kernel_launch(void* const* d_in, const int* in_sizes, int n_in,
                              void* d_out, int out_size){
    const float* test_reps = (const float*)d_in[0];
    const float* support   = (const float*)d_in[1];
    const float* tgt       = (const float*)d_in[4];
    float* out_scores = (float*)d_out;                                  // (B,T,NT)
    float* out_proto  = (float*)d_out + (size_t)BB*TT*NTAG;             // (B,NT,D)

    k_mean  <<<(BB*TT*DD/4 + 255)/256, 256>>>(test_reps);
    k_labels<<<BB, 256>>>(tgt);
    k_proto <<<dim3(BB, NTAG), 256>>>(support, out_proto);
    k_gemm  <<<dim3(CH, BB), 256>>>(support);
    k_final <<<dim3(BB, 2), 256>>>(tgt, out_proto, out_scores);
}

// round 4
// speedup vs baseline: 1.4553x; 1.4553x over previous
#include <cuda_runtime.h>
#include <cstdint>

#define BB 32
#define KKS 10
#define TT 128
#define LLS 128
#define DD 1024
#define NTAG 32
#define SS (KKS*LLS)     // 1280
#define CH 20            // chunks of 64 support rows
#define CROWS 64

typedef unsigned long long ull;

// ---------------- scratch (device globals; no allocation) ----------------
__device__ float  g_test_mean[BB*TT*DD];     // (B,T,D) 16 MB
__device__ int    g_list[BB*NTAG*256];       // per (b,tag) support-row index lists
__device__ int    g_cnt[BB*NTAG];
__device__ float2 g_cmin[BB*TT*CH];          // per-chunk (minval, idx-as-float)

// ---------------- kernel 1: test_mean = mean_k test_reps ----------------
__global__ void k_mean(const float* __restrict__ x){
    int idx = blockIdx.x*blockDim.x + threadIdx.x;
    const int n4 = BB*TT*DD/4;
    if (idx >= n4) return;
    int b   = idx / (TT*DD/4);
    int rem = idx - b*(TT*DD/4);
    const float4* p = (const float4*)x + (size_t)b*KKS*(TT*DD/4) + rem;
    float4 a = make_float4(0.f,0.f,0.f,0.f);
#pragma unroll
    for (int k=0;k<KKS;k++){
        float4 v = p[(size_t)k*(TT*DD/4)];
        a.x+=v.x; a.y+=v.y; a.z+=v.z; a.w+=v.w;
    }
    const float s = 1.0f/(float)KKS;
    a.x*=s; a.y*=s; a.z*=s; a.w*=s;
    ((float4*)g_test_mean)[idx] = a;
}

// ---------------- kernel 2: labels + per-tag index lists (warp ballot compaction) ----------------
__global__ __launch_bounds__(256) void k_labels(const float* __restrict__ tgt){
    __shared__ int lab[SS];
    int b = blockIdx.x, tid = threadIdx.x;
    for (int s = tid; s < SS; s += 256){
        const float* row = tgt + ((size_t)b*SS + s)*NTAG;
        float bv = row[0]; int bi = 0;
#pragma unroll
        for (int n=1;n<NTAG;n++){ float v=row[n]; if (v>bv){bv=v;bi=n;} }
        lab[s] = bi;
    }
    __syncthreads();
    int w = tid >> 5, lane = tid & 31;
    for (int n = w; n < NTAG; n += 8){
        int c = 0;
        int* lst = g_list + ((size_t)b*NTAG + n)*256;
        for (int s0 = 0; s0 < SS; s0 += 32){
            int s = s0 + lane;
            bool m = (lab[s] == n);
            unsigned bal = __ballot_sync(0xffffffffu, m);
            if (m && c + __popc(bal & ((1u<<lane)-1u)) < 256)
                lst[c + __popc(bal & ((1u<<lane)-1u))] = s;
            c += __popc(bal);
        }
        if (lane == 0) g_cnt[b*NTAG + n] = (c < 256) ? c : 256;
    }
}

// ---------------- kernel 3: prototypes = gather-sum / (count+1e-4) ----------------
__global__ __launch_bounds__(256) void k_proto(const float* __restrict__ sup,
                                               float* __restrict__ proto){
    int b = blockIdx.x, n = blockIdx.y, tid = threadIdx.x;
    __shared__ int sl[256];
    int cnt = g_cnt[b*NTAG + n];
    const int* lst = g_list + ((size_t)b*NTAG + n)*256;
    sl[tid] = (tid < cnt) ? lst[tid] : 0;
    __syncthreads();
    float4 acc = make_float4(0.f,0.f,0.f,0.f);
    const float4* base = (const float4*)(sup + (size_t)b*SS*DD) + tid;
    int j = 0;
    for (; j+4 <= cnt; j += 4){
        float4 v0 = base[(size_t)sl[j+0]*(DD/4)];
        float4 v1 = base[(size_t)sl[j+1]*(DD/4)];
        float4 v2 = base[(size_t)sl[j+2]*(DD/4)];
        float4 v3 = base[(size_t)sl[j+3]*(DD/4)];
        acc.x += (v0.x+v1.x) + (v2.x+v3.x);
        acc.y += (v0.y+v1.y) + (v2.y+v3.y);
        acc.z += (v0.z+v1.z) + (v2.z+v3.z);
        acc.w += (v0.w+v1.w) + (v2.w+v3.w);
    }
    for (; j < cnt; j++){
        float4 v = base[(size_t)sl[j]*(DD/4)];
        acc.x+=v.x; acc.y+=v.y; acc.z+=v.z; acc.w+=v.w;
    }
    float inv = 1.0f/((float)cnt + 1e-4f);
    acc.x*=inv; acc.y*=inv; acc.z*=inv; acc.w*=inv;
    ((float4*)(proto + ((size_t)b*NTAG + n)*DD))[tid] = acc;
}

// ---------------- kernel 4: fp32x2 SGEMM (128T x 64S x 1024) + chunk argmin ----------------
// grid (20, 32); 128 threads; 8x8 register tile; R2 smem layout (k-major, no dup, no pad).
// thread (tx,ty): rows ty*8..ty*8+7, cols tx*8..tx*8+7.
__global__ __launch_bounds__(128,3) void k_gemm(const float* __restrict__ sup){
    const int ch = blockIdx.x, b = blockIdx.y;
    const int tid = threadIdx.x;
    const int tx = tid & 7, ty = tid >> 3;
    __shared__ float As[2][16][128];     // 16 KB
    __shared__ float Bs[2][16][64];      //  8 KB
    __shared__ float snorm[CROWS];

    const float* A  = g_test_mean + (size_t)b*TT*DD;
    const float* Bp = sup + ((size_t)b*SS + (size_t)ch*CROWS)*DD;

    // A loader: 512 float4/tile -> 4 per thread. B: 256 float4 -> 2 per thread.
    int am[4], ak[4], bm[2], bk[2];
#pragma unroll
    for (int q=0;q<4;q++){ int j = tid + q*128; am[q]=j>>2; ak[q]=(j&3)*4; }
#pragma unroll
    for (int q=0;q<2;q++){ int j = tid + q*128; bm[q]=j>>2; bk[q]=(j&3)*4; }
    const float* pA0 = A  + (size_t)am[0]*DD + ak[0];
    const float* pA1 = A  + (size_t)am[1]*DD + ak[1];
    const float* pA2 = A  + (size_t)am[2]*DD + ak[2];
    const float* pA3 = A  + (size_t)am[3]*DD + ak[3];
    const float* pB0 = Bp + (size_t)bm[0]*DD + bk[0];
    const float* pB1 = Bp + (size_t)bm[1]*DD + bk[1];

    ull acc[8][4];
#pragma unroll
    for (int i=0;i<8;i++)
#pragma unroll
        for (int c=0;c<4;c++) acc[i][c]=0ull;
    float nrm0 = 0.f, nrm1 = 0.f;

    float4 ra0 = *(const float4*)pA0;
    float4 ra1 = *(const float4*)pA1;
    float4 ra2 = *(const float4*)pA2;
    float4 ra3 = *(const float4*)pA3;
    float4 rb0 = *(const float4*)pB0;
    float4 rb1 = *(const float4*)pB1;
    nrm0 += rb0.x*rb0.x + rb0.y*rb0.y + rb0.z*rb0.z + rb0.w*rb0.w;
    nrm1 += rb1.x*rb1.x + rb1.y*rb1.y + rb1.z*rb1.z + rb1.w*rb1.w;
    As[0][ak[0]+0][am[0]]=ra0.x; As[0][ak[0]+1][am[0]]=ra0.y; As[0][ak[0]+2][am[0]]=ra0.z; As[0][ak[0]+3][am[0]]=ra0.w;
    As[0][ak[1]+0][am[1]]=ra1.x; As[0][ak[1]+1][am[1]]=ra1.y; As[0][ak[1]+2][am[1]]=ra1.z; As[0][ak[1]+3][am[1]]=ra1.w;
    As[0][ak[2]+0][am[2]]=ra2.x; As[0][ak[2]+1][am[2]]=ra2.y; As[0][ak[2]+2][am[2]]=ra2.z; As[0][ak[2]+3][am[2]]=ra2.w;
    As[0][ak[3]+0][am[3]]=ra3.x; As[0][ak[3]+1][am[3]]=ra3.y; As[0][ak[3]+2][am[3]]=ra3.z; As[0][ak[3]+3][am[3]]=ra3.w;
    Bs[0][bk[0]+0][bm[0]]=rb0.x; Bs[0][bk[0]+1][bm[0]]=rb0.y; Bs[0][bk[0]+2][bm[0]]=rb0.z; Bs[0][bk[0]+3][bm[0]]=rb0.w;
    Bs[0][bk[1]+0][bm[1]]=rb1.x; Bs[0][bk[1]+1][bm[1]]=rb1.y; Bs[0][bk[1]+2][bm[1]]=rb1.z; Bs[0][bk[1]+3][bm[1]]=rb1.w;
    __syncthreads();

    for (int kt=0; kt<DD/16; kt++){
        const int buf = kt & 1;
        if (kt < DD/16-1){
            const int off = (kt+1)*16;
            ra0 = *(const float4*)(pA0+off);
            ra1 = *(const float4*)(pA1+off);
            ra2 = *(const float4*)(pA2+off);
            ra3 = *(const float4*)(pA3+off);
            rb0 = *(const float4*)(pB0+off);
            rb1 = *(const float4*)(pB1+off);
            nrm0 += rb0.x*rb0.x + rb0.y*rb0.y + rb0.z*rb0.z + rb0.w*rb0.w;
            nrm1 += rb1.x*rb1.x + rb1.y*rb1.y + rb1.z*rb1.z + rb1.w*rb1.w;
        }
#pragma unroll
        for (int kk=0;kk<16;kk++){
            float4 a0 = *(const float4*)&As[buf][kk][ty*8];
            float4 a1 = *(const float4*)&As[buf][kk][ty*8+4];
            const ull* br = (const ull*)&Bs[buf][kk][tx*8];
            ull b0 = br[0], b1 = br[1], b2 = br[2], b3 = br[3];
            float av[8] = {a0.x,a0.y,a0.z,a0.w,a1.x,a1.y,a1.z,a1.w};
#pragma unroll
            for (int i=0;i<8;i++){
                ull aa;
                asm("mov.b64 %0, {%1, %1};" : "=l"(aa) : "f"(av[i]));
                asm("fma.rn.f32x2 %0, %1, %2, %0;" : "+l"(acc[i][0]) : "l"(aa), "l"(b0));
                asm("fma.rn.f32x2 %0, %1, %2, %0;" : "+l"(acc[i][1]) : "l"(aa), "l"(b1));
                asm("fma.rn.f32x2 %0, %1, %2, %0;" : "+l"(acc[i][2]) : "l"(aa), "l"(b2));
                asm("fma.rn.f32x2 %0, %1, %2, %0;" : "+l"(acc[i][3]) : "l"(aa), "l"(b3));
            }
        }
        if (kt < DD/16-1){
            const int nb = buf^1;
            As[nb][ak[0]+0][am[0]]=ra0.x; As[nb][ak[0]+1][am[0]]=ra0.y; As[nb][ak[0]+2][am[0]]=ra0.z; As[nb][ak[0]+3][am[0]]=ra0.w;
            As[nb][ak[1]+0][am[1]]=ra1.x; As[nb][ak[1]+1][am[1]]=ra1.y; As[nb][ak[1]+2][am[1]]=ra1.z; As[nb][ak[1]+3][am[1]]=ra1.w;
            As[nb][ak[2]+0][am[2]]=ra2.x; As[nb][ak[2]+1][am[2]]=ra2.y; As[nb][ak[2]+2][am[2]]=ra2.z; As[nb][ak[2]+3][am[2]]=ra2.w;
            As[nb][ak[3]+0][am[3]]=ra3.x; As[nb][ak[3]+1][am[3]]=ra3.y; As[nb][ak[3]+2][am[3]]=ra3.z; As[nb][ak[3]+3][am[3]]=ra3.w;
            Bs[nb][bk[0]+0][bm[0]]=rb0.x; Bs[nb][bk[0]+1][bm[0]]=rb0.y; Bs[nb][bk[0]+2][bm[0]]=rb0.z; Bs[nb][bk[0]+3][bm[0]]=rb0.w;
            Bs[nb][bk[1]+0][bm[1]]=rb1.x; Bs[nb][bk[1]+1][bm[1]]=rb1.y; Bs[nb][bk[1]+2][bm[1]]=rb1.z; Bs[nb][bk[1]+3][bm[1]]=rb1.w;
        }
        __syncthreads();
    }

    // support-row norms: 4 partials per row (lanes tid&3), two rows per thread
    nrm0 += __shfl_xor_sync(0xffffffffu, nrm0, 2);
    nrm0 += __shfl_xor_sync(0xffffffffu, nrm0, 1);
    nrm1 += __shfl_xor_sync(0xffffffffu, nrm1, 2);
    nrm1 += __shfl_xor_sync(0xffffffffu, nrm1, 1);
    if ((tid & 3) == 0){ snorm[bm[0]] = nrm0; snorm[bm[1]] = nrm1; }
    __syncthreads();

    // score = |s|^2 - 2*dot ; per-row chunk argmin, first-min tie-break
#pragma unroll
    for (int i=0;i<8;i++){
        float bv = 3.4e38f; int bi = 1<<30;
#pragma unroll
        for (int c=0;c<4;c++){
            float2 d = *(float2*)&acc[i][c];
            int n0 = tx*8 + c*2;
            float s0 = snorm[n0]   - 2.f*d.x;
            float s1 = snorm[n0+1] - 2.f*d.y;
            if (s0 < bv || (s0==bv && n0   < bi)) { bv=s0; bi=n0;   }
            if (s1 < bv || (s1==bv && n0+1 < bi)) { bv=s1; bi=n0+1; }
        }
#pragma unroll
        for (int o=4;o;o>>=1){
            float ov = __shfl_down_sync(0xffffffffu, bv, o, 8);
            int   oi = __shfl_down_sync(0xffffffffu, bi, o, 8);
            if (ov < bv || (ov==bv && oi<bi)) { bv=ov; bi=oi; }
        }
        if (tx==0){
            int m = ty*8 + i;
            g_cmin[((size_t)b*TT+m)*CH + ch] = make_float2(bv, __int_as_float(ch*CROWS + bi));
        }
    }
}

// ---------------- kernel 5: nn-reduce + scores GEMM fused ----------------
__global__ __launch_bounds__(256) void k_final(const float* __restrict__ tgt,
                                               const float* __restrict__ proto,
                                               float* __restrict__ outs){
    __shared__ float As[16][64];
    __shared__ float Bs[16][32];
    __shared__ int   snn[64];
    int b = blockIdx.x, half = blockIdx.y, tid = threadIdx.x;
    const int trow = tid & 63, tg = tid >> 6;

    if (tid < 64){
        const float2* e = &g_cmin[((size_t)b*TT + half*64 + tid)*CH];
        float2 v0 = e[0];
        float bv = v0.x; int bi = __float_as_int(v0.y);
#pragma unroll
        for (int c=1;c<CH;c++){
            float2 v = e[c];
            if (v.x < bv){ bv = v.x; bi = __float_as_int(v.y); }
        }
        snn[tid] = bi;
    }

    const float* Ab = g_test_mean + ((size_t)b*TT + half*64)*DD;
    const float* Pb = proto + (size_t)b*NTAG*DD;
    const int ar = tid>>2, ak = (tid&3)*4;

    ull acc[4];
#pragma unroll
    for (int i=0;i<4;i++) acc[i]=0ull;

    for (int kt=0; kt<DD/16; kt++){
        __syncthreads();
        {
            float4 va = *(const float4*)(Ab + (size_t)ar*DD + kt*16 + ak);
            As[ak+0][ar]=va.x; As[ak+1][ar]=va.y; As[ak+2][ar]=va.z; As[ak+3][ar]=va.w;
            if (tid < 128){
                float4 vb = *(const float4*)(Pb + (size_t)ar*DD + kt*16 + ak);
                Bs[ak+0][ar]=vb.x; Bs[ak+1][ar]=vb.y; Bs[ak+2][ar]=vb.z; Bs[ak+3][ar]=vb.w;
            }
        }
        __syncthreads();
#pragma unroll
        for (int kk=0;kk<16;kk++){
            float a = As[kk][trow];
            const ull* br = (const ull*)&Bs[kk][tg*8];
            ull aa;
            asm("mov.b64 %0, {%1, %1};" : "=l"(aa) : "f"(a));
#pragma unroll
            for (int i=0;i<4;i++)
                asm("fma.rn.f32x2 %0, %1, %2, %0;" : "+l"(acc[i]) : "l"(aa), "l"(br[i]));
        }
    }
    __syncthreads();

    int nn = snn[trow];
    const float4* tp = (const float4*)(tgt + ((size_t)b*SS + nn)*NTAG + tg*8);
    float4 t0 = tp[0], t1 = tp[1];
    float2 d0 = *(float2*)&acc[0], d1 = *(float2*)&acc[1];
    float2 d2 = *(float2*)&acc[2], d3 = *(float2*)&acc[3];
    float4 o0 = make_float4(t0.x+0.5f*d0.x, t0.y+0.5f*d0.y, t0.z+0.5f*d1.x, t0.w+0.5f*d1.y);
    float4 o1 = make_float4(t1.x+0.5f*d2.x, t1.y+0.5f*d2.y, t1.z+0.5f*d3.x, t1.w+0.5f*d3.y);
    float4* op = (float4*)(outs + ((size_t)b*TT + half*64 + trow)*NTAG + tg*8);
    op[0] = o0; op[1] = o1;
}

// ---------------- launch ----------------
extern "C" void kernel_launch(void* const* d_in, const int* in_sizes, int n_in,
                              void* d_out, int out_size){
    const float* test_reps = (const float*)d_in[0];
    const float* support   = (const float*)d_in[1];
    const float* tgt       = (const float*)d_in[4];
    float* out_scores = (float*)d_out;                                  // (B,T,NT)
    float* out_proto  = (float*)d_out + (size_t)BB*TT*NTAG;             // (B,NT,D)

    k_mean  <<<(BB*TT*DD/4 + 255)/256, 256>>>(test_reps);
    k_labels<<<BB, 256>>>(tgt);
    k_proto <<<dim3(BB, NTAG), 256>>>(support, out_proto);
    k_gemm  <<<dim3(CH, BB), 128>>>(support);
    k_final <<<dim3(BB, 2), 256>>>(tgt, out_proto, out_scores);
}

// round 7
// speedup vs baseline: 2.5372x; 1.7434x over previous
#include <cuda_runtime.h>
#include <cuda_bf16.h>
#include <cstdint>

#define BB 32
#define KKS 10
#define TT 128
#define LLS 128
#define DD 1024
#define NTAG 32
#define SS (KKS*LLS)     // 1280
#define CH 20            // chunks of 64 support rows
#define CROWS 64

typedef unsigned long long ull;

// ---- dynamic smem layout for k_gemm (1024-aligned tiles, 48KB exactly) ----
#define OFF_AHI   0
#define OFF_ALO   16384
#define OFF_BHI   32768
#define OFF_BLO   40960
#define GEMM_SMEM 49152
// post-loop overlay (inside OFF_AHI region, used only after MMA loop):
//   snorm: [0,256) ; rmin: [256, 256+128*2*8)

// ---------------- scratch (device globals; no allocation) ----------------
__device__ float  g_test_mean[BB*TT*DD];       // (B,T,D) fp32 16 MB
__device__ uint4  g_ahi[BB*TT*DD/8];           // test_mean hi bf16
__device__ uint4  g_alo[BB*TT*DD/8];           // test_mean lo bf16
__device__ int    g_list[BB*NTAG*256];
__device__ int    g_cnt[BB*NTAG];
__device__ float2 g_cmin[BB*TT*CH];

// ---------------- helpers ----------------
__device__ __forceinline__ uint32_t smem_u32(const void* p){
    uint32_t a;
    asm("{ .reg .u64 t; cvta.to.shared.u64 t, %1; cvt.u32.u64 %0, t; }" : "=r"(a) : "l"(p));
    return a;
}
__device__ __forceinline__ void bf16_split4(float4 v, uint32_t& h01, uint32_t& h23,
                                            uint32_t& l01, uint32_t& l23){
    asm("cvt.rn.bf16x2.f32 %0, %1, %2;" : "=r"(h01) : "f"(v.y), "f"(v.x));
    asm("cvt.rn.bf16x2.f32 %0, %1, %2;" : "=r"(h23) : "f"(v.w), "f"(v.z));
    float hx = __uint_as_float(h01<<16), hy = __uint_as_float(h01 & 0xffff0000u);
    float hz = __uint_as_float(h23<<16), hw = __uint_as_float(h23 & 0xffff0000u);
    asm("cvt.rn.bf16x2.f32 %0, %1, %2;" : "=r"(l01) : "f"(v.y-hy), "f"(v.x-hx));
    asm("cvt.rn.bf16x2.f32 %0, %1, %2;" : "=r"(l23) : "f"(v.w-hw), "f"(v.z-hz));
}
__device__ __forceinline__ void ldm_x4(uint32_t r[4], uint32_t addr){
    asm volatile("ldmatrix.sync.aligned.m8n8.x4.shared.b16 {%0,%1,%2,%3}, [%4];"
        : "=r"(r[0]),"=r"(r[1]),"=r"(r[2]),"=r"(r[3]) : "r"(addr));
}
__device__ __forceinline__ void mma_bf16(float c[4], const uint32_t a[4],
                                         uint32_t b0, uint32_t b1){
    asm volatile("mma.sync.aligned.m16n8k16.row.col.f32.bf16.bf16.f32 "
        "{%0,%1,%2,%3}, {%4,%5,%6,%7}, {%8,%9}, {%0,%1,%2,%3};"
        : "+f"(c[0]),"+f"(c[1]),"+f"(c[2]),"+f"(c[3])
        : "r"(a[0]),"r"(a[1]),"r"(a[2]),"r"(a[3]), "r"(b0),"r"(b1));
}
__device__ __forceinline__ uint32_t sw128(uint32_t off){ return off ^ ((off>>3)&0x70); }

// ---------------- kernel 1: test_mean (fp32 + bf16 hi/lo) ----------------
__global__ void k_mean(const float* __restrict__ x){
    int idx = blockIdx.x*blockDim.x + threadIdx.x;
    const int n4 = BB*TT*DD/4;
    if (idx >= n4) return;
    int b   = idx / (TT*DD/4);
    int rem = idx - b*(TT*DD/4);
    const float4* p = (const float4*)x + (size_t)b*KKS*(TT*DD/4) + rem;
    float4 a = make_float4(0.f,0.f,0.f,0.f);
#pragma unroll
    for (int k=0;k<KKS;k++){
        float4 v = p[(size_t)k*(TT*DD/4)];
        a.x+=v.x; a.y+=v.y; a.z+=v.z; a.w+=v.w;
    }
    const float s = 1.0f/(float)KKS;
    a.x*=s; a.y*=s; a.z*=s; a.w*=s;
    ((float4*)g_test_mean)[idx] = a;
    uint32_t h01,h23,l01,l23;
    bf16_split4(a, h01,h23,l01,l23);
    ((uint2*)g_ahi)[idx] = make_uint2(h01,h23);
    ((uint2*)g_alo)[idx] = make_uint2(l01,l23);
}

// ---------------- kernel 2: labels + per-tag index lists ----------------
__global__ __launch_bounds__(256) void k_labels(const float* __restrict__ tgt){
    __shared__ int lab[SS];
    int b = blockIdx.x, tid = threadIdx.x;
    for (int s = tid; s < SS; s += 256){
        const float* row = tgt + ((size_t)b*SS + s)*NTAG;
        float bv = row[0]; int bi = 0;
#pragma unroll
        for (int n=1;n<NTAG;n++){ float v=row[n]; if (v>bv){bv=v;bi=n;} }
        lab[s] = bi;
    }
    __syncthreads();
    int w = tid >> 5, lane = tid & 31;
    for (int n = w; n < NTAG; n += 8){
        int c = 0;
        int* lst = g_list + ((size_t)b*NTAG + n)*256;
        for (int s0 = 0; s0 < SS; s0 += 32){
            int s = s0 + lane;
            bool m = (lab[s] == n);
            unsigned bal = __ballot_sync(0xffffffffu, m);
            if (m && c + __popc(bal & ((1u<<lane)-1u)) < 256)
                lst[c + __popc(bal & ((1u<<lane)-1u))] = s;
            c += __popc(bal);
        }
        if (lane == 0) g_cnt[b*NTAG + n] = (c < 256) ? c : 256;
    }
}

// ---------------- kernel 3: prototypes ----------------
__global__ __launch_bounds__(256) void k_proto(const float* __restrict__ sup,
                                               float* __restrict__ proto){
    int b = blockIdx.x, n = blockIdx.y, tid = threadIdx.x;
    __shared__ int sl[256];
    int cnt = g_cnt[b*NTAG + n];
    const int* lst = g_list + ((size_t)b*NTAG + n)*256;
    sl[tid] = (tid < cnt) ? lst[tid] : 0;
    __syncthreads();
    float4 acc = make_float4(0.f,0.f,0.f,0.f);
    const float4* base = (const float4*)(sup + (size_t)b*SS*DD) + tid;
    int j = 0;
    for (; j+4 <= cnt; j += 4){
        float4 v0 = base[(size_t)sl[j+0]*(DD/4)];
        float4 v1 = base[(size_t)sl[j+1]*(DD/4)];
        float4 v2 = base[(size_t)sl[j+2]*(DD/4)];
        float4 v3 = base[(size_t)sl[j+3]*(DD/4)];
        acc.x += (v0.x+v1.x) + (v2.x+v3.x);
        acc.y += (v0.y+v1.y) + (v2.y+v3.y);
        acc.z += (v0.z+v1.z) + (v2.z+v3.z);
        acc.w += (v0.w+v1.w) + (v2.w+v3.w);
    }
    for (; j < cnt; j++){
        float4 v = base[(size_t)sl[j]*(DD/4)];
        acc.x+=v.x; acc.y+=v.y; acc.z+=v.z; acc.w+=v.w;
    }
    float inv = 1.0f/((float)cnt + 1e-4f);
    acc.x*=inv; acc.y*=inv; acc.z*=inv; acc.w*=inv;
    ((float4*)(proto + ((size_t)b*NTAG + n)*DD))[tid] = acc;
}

// ---------------- kernel 4: HMMA bf16x3 GEMM (128 x 64 x 1024) + argmin ----------------
// grid (20, 32); 256 threads = 8 warps (4m x 2n), warp tile 32x32. No static smem.
__global__ __launch_bounds__(256,2) void k_gemm(const float* __restrict__ sup){
    extern __shared__ char smem[];
    const uint32_t sb = smem_u32(smem);
    const int ch = blockIdx.x, b = blockIdx.y;
    const int tid = threadIdx.x;
    const int lane = tid & 31, wid = tid >> 5;
    const int warp_m = wid & 3, warp_n = wid >> 2;

    const uint4*  A4h = g_ahi + (size_t)b*(TT*DD/8);
    const uint4*  A4l = g_alo + (size_t)b*(TT*DD/8);
    const float4* B4  = (const float4*)(sup + ((size_t)b*SS + (size_t)ch*CROWS)*DD);

    // loader geometry (fixed per thread)
    int amq[4], ajq[4], brq[4], bcq[4];
    uint32_t asw[4], bsw[4];
#pragma unroll
    for (int q=0;q<4;q++){
        int jj = tid + q*256;
        amq[q] = jj >> 3;  ajq[q] = jj & 7;                 // A: row m, uint4 col j
        asw[q] = sw128((uint32_t)(amq[q]*128 + ajq[q]*16));
        brq[q] = jj >> 4;  bcq[q] = jj & 15;                // B: row r, float4 col c4
        bsw[q] = sw128((uint32_t)(brq[q]*128 + bcq[q]*8));
    }

    float acc[2][4][4];
#pragma unroll
    for (int mt=0;mt<2;mt++)
#pragma unroll
        for (int nn=0;nn<4;nn++)
#pragma unroll
            for (int e=0;e<4;e++) acc[mt][nn][e]=0.f;
    float nrm[4] = {0.f,0.f,0.f,0.f};

    // ldmatrix address components (fixed per thread)
    const int a_row = (lane & 15);                       // + warp_m*32 + mt*16
    const int a_kb  = (lane >> 4) * 16;                  // + ks*32
    const int b_row = (lane & 7) + ((lane >> 4) << 3);   // + warp_n*32
    const int b_kb  = ((lane >> 3) & 1) * 16;            // + ks*32

    for (int kt = 0; kt < 16; kt++){
        __syncthreads();
        // 12-deep LDG batch, then convert + STS
        uint4 rAh[4], rAl[4]; float4 rB[4];
#pragma unroll
        for (int q=0;q<4;q++){
            rAh[q] = A4h[amq[q]*128 + kt*8 + ajq[q]];
            rAl[q] = A4l[amq[q]*128 + kt*8 + ajq[q]];
            rB[q]  = B4[(size_t)brq[q]*256 + kt*16 + bcq[q]];
        }
#pragma unroll
        for (int q=0;q<4;q++){
            *(uint4*)(smem + OFF_AHI + asw[q]) = rAh[q];
            *(uint4*)(smem + OFF_ALO + asw[q]) = rAl[q];
            float4 v = rB[q];
            nrm[q] += v.x*v.x + v.y*v.y + v.z*v.z + v.w*v.w;
            uint32_t h01,h23,l01,l23;
            bf16_split4(v, h01,h23,l01,l23);
            *(uint2*)(smem + OFF_BHI + bsw[q]) = make_uint2(h01,h23);
            *(uint2*)(smem + OFF_BLO + bsw[q]) = make_uint2(l01,l23);
        }
        __syncthreads();
#pragma unroll
        for (int ks=0; ks<4; ks++){
            uint32_t ah[2][4], al[2][4], bh[2][4], bl[2][4];
#pragma unroll
            for (int mt=0;mt<2;mt++){
                uint32_t off = sw128((uint32_t)((warp_m*32 + mt*16 + a_row)*128 + ks*32 + a_kb));
                ldm_x4(ah[mt], sb + OFF_AHI + off);
                ldm_x4(al[mt], sb + OFF_ALO + off);
            }
#pragma unroll
            for (int p=0;p<2;p++){
                uint32_t off = sw128((uint32_t)((warp_n*32 + p*16 + b_row)*128 + ks*32 + b_kb));
                ldm_x4(bh[p], sb + OFF_BHI + off);
                ldm_x4(bl[p], sb + OFF_BLO + off);
            }
#pragma unroll
            for (int mt=0;mt<2;mt++)
#pragma unroll
                for (int nn=0;nn<4;nn++){
                    const int p = nn>>1, h = (nn&1)*2;
                    mma_bf16(acc[mt][nn], ah[mt], bh[p][h], bh[p][h+1]);
                    mma_bf16(acc[mt][nn], ah[mt], bl[p][h], bl[p][h+1]);
                    mma_bf16(acc[mt][nn], al[mt], bh[p][h], bh[p][h+1]);
                }
        }
    }
    __syncthreads();   // all tile reads done before overlay writes

    float*  snorm_s = (float*)(smem);          // 64 floats
    float2* rmin_s  = (float2*)(smem + 256);   // [128][2]

    // support-row norms: reduce 16-lane groups; row = (tid>>4) + q*16
#pragma unroll
    for (int q=0;q<4;q++){
        float v = nrm[q];
        v += __shfl_xor_sync(0xffffffffu, v, 8, 16);
        v += __shfl_xor_sync(0xffffffffu, v, 4, 16);
        v += __shfl_xor_sync(0xffffffffu, v, 2, 16);
        v += __shfl_xor_sync(0xffffffffu, v, 1, 16);
        if ((tid & 15) == 0) snorm_s[(tid>>4) + q*16] = v;
    }
    __syncthreads();

    // epilogue: per-row argmin within warp's 32 cols, first-min tie-break
#pragma unroll
    for (int mt=0;mt<2;mt++){
#pragma unroll
        for (int rh=0;rh<2;rh++){
            int m = warp_m*32 + mt*16 + (lane>>2) + rh*8;
            float bv = 3.4e38f; int bi = 1<<30;
#pragma unroll
            for (int nn=0;nn<4;nn++){
#pragma unroll
                for (int e=0;e<2;e++){
                    int n = warp_n*32 + nn*8 + 2*(lane&3) + e;
                    float s = snorm_s[n] - 2.f*acc[mt][nn][rh*2+e];
                    if (s < bv || (s==bv && n < bi)){ bv=s; bi=n; }
                }
            }
#pragma unroll
            for (int o=2;o;o>>=1){
                float ov = __shfl_down_sync(0xffffffffu, bv, o, 4);
                int   oi = __shfl_down_sync(0xffffffffu, bi, o, 4);
                if (ov < bv || (ov==bv && oi<bi)){ bv=ov; bi=oi; }
            }
            if ((lane&3)==0) rmin_s[m*2 + warp_n] = make_float2(bv, __int_as_float(bi));
        }
    }
    __syncthreads();
    if (tid < TT){
        float2 v0 = rmin_s[tid*2 + 0], v1 = rmin_s[tid*2 + 1];
        float bv = v0.x; int bi = __float_as_int(v0.y);
        if (v1.x < bv){ bv = v1.x; bi = __float_as_int(v1.y); }
        g_cmin[((size_t)b*TT + tid)*CH + ch] = make_float2(bv, __int_as_float(ch*CROWS + bi));
    }
}

// ---------------- kernel 5: nn-reduce + scores GEMM fused ----------------
__global__ __launch_bounds__(256) void k_final(const float* __restrict__ tgt,
                                               const float* __restrict__ proto,
                                               float* __restrict__ outs){
    __shared__ float As[16][64];
    __shared__ float Bs[16][32];
    __shared__ int   snn[64];
    int b = blockIdx.x, half = blockIdx.y, tid = threadIdx.x;
    const int trow = tid & 63, tg = tid >> 6;

    if (tid < 64){
        const float2* e = &g_cmin[((size_t)b*TT + half*64 + tid)*CH];
        float2 v0 = e[0];
        float bv = v0.x; int bi = __float_as_int(v0.y);
#pragma unroll
        for (int c=1;c<CH;c++){
            float2 v = e[c];
            if (v.x < bv){ bv = v.x; bi = __float_as_int(v.y); }
        }
        snn[tid] = bi;
    }

    const float* Ab = g_test_mean + ((size_t)b*TT + half*64)*DD;
    const float* Pb = proto + (size_t)b*NTAG*DD;
    const int ar = tid>>2, ak = (tid&3)*4;

    ull acc[4];
#pragma unroll
    for (int i=0;i<4;i++) acc[i]=0ull;

    for (int kt=0; kt<DD/16; kt++){
        __syncthreads();
        {
            float4 va = *(const float4*)(Ab + (size_t)ar*DD + kt*16 + ak);
            As[ak+0][ar]=va.x; As[ak+1][ar]=va.y; As[ak+2][ar]=va.z; As[ak+3][ar]=va.w;
            if (tid < 128){
                float4 vb = *(const float4*)(Pb + (size_t)ar*DD + kt*16 + ak);
                Bs[ak+0][ar]=vb.x; Bs[ak+1][ar]=vb.y; Bs[ak+2][ar]=vb.z; Bs[ak+3][ar]=vb.w;
            }
        }
        __syncthreads();
#pragma unroll
        for (int kk=0;kk<16;kk++){
            float a = As[kk][trow];
            const ull* br = (const ull*)&Bs[kk][tg*8];
            ull aa;
            asm("mov.b64 %0, {%1, %1};" : "=l"(aa) : "f"(a));
#pragma unroll
            for (int i=0;i<4;i++)
                asm("fma.rn.f32x2 %0, %1, %2, %0;" : "+l"(acc[i]) : "l"(aa), "l"(br[i]));
        }
    }
    __syncthreads();

    int nn = snn[trow];
    const float4* tp = (const float4*)(tgt + ((size_t)b*SS + nn)*NTAG + tg*8);
    float4 t0 = tp[0], t1 = tp[1];
    float2 d0 = *(float2*)&acc[0], d1 = *(float2*)&acc[1];
    float2 d2 = *(float2*)&acc[2], d3 = *(float2*)&acc[3];
    float4 o0 = make_float4(t0.x+0.5f*d0.x, t0.y+0.5f*d0.y, t0.z+0.5f*d1.x, t0.w+0.5f*d1.y);
    float4 o1 = make_float4(t1.x+0.5f*d2.x, t1.y+0.5f*d2.y, t1.z+0.5f*d3.x, t1.w+0.5f*d3.y);
    float4* op = (float4*)(outs + ((size_t)b*TT + half*64 + trow)*NTAG + tg*8);
    op[0] = o0; op[1] = o1;
}

// ---------------- launch ----------------
extern "C" void kernel_launch(void* const* d_in, const int* in_sizes, int n_in,
                              void* d_out, int out_size){
    const float* test_reps = (const float*)d_in[0];
    const float* support   = (const float*)d_in[1];
    const float* tgt       = (const float*)d_in[4];
    float* out_scores = (float*)d_out;                                  // (B,T,NT)
    float* out_proto  = (float*)d_out + (size_t)BB*TT*NTAG;             // (B,NT,D)

    k_mean  <<<(BB*TT*DD/4 + 255)/256, 256>>>(test_reps);
    k_labels<<<BB, 256>>>(tgt);
    k_proto <<<dim3(BB, NTAG), 256>>>(support, out_proto);
    k_gemm  <<<dim3(CH, BB), 256, GEMM_SMEM>>>(support);
    k_final <<<dim3(BB, 2), 256>>>(tgt, out_proto, out_scores);
}